// round 1
// baseline (speedup 1.0000x reference)
#include <cuda_runtime.h>
#include <math.h>

#define BB 16
#define NN 1024
#define HD 128
#define NEGV (-9000000000000000.0f)
#define ALPHAV 0.2f

// ---------------- scratch (device globals; no allocation allowed) ----------------
__device__ float g_Y [BB*NN*HD];   // X@W intermediate
__device__ float g_X1[BB*NN*HD];
__device__ float g_X2[BB*NN*HD];
__device__ float g_Wh[BB*NN*HD];
__device__ float g_x3[BB*NN*HD];
__device__ float g_s1[BB*NN];
__device__ float g_s2[BB*NN];
__device__ float g_satt[BB*NN];
__device__ float g_psum[BB*16*HD];
__device__ float g_pmax[BB*16*HD];

// ============================================================================
// Feature GEMM: C(R x 128) = X(R x 128) @ W(128 x 128), R = B*N
// Tile: 64 rows x 128 cols, BK = 32, 256 threads, 8x4 microtile per thread.
// SRC: 0 = external ptr, 1 = g_X1, 2 = g_X2 ; DST: 0 = g_Y, 1 = g_Wh
// ============================================================================
template<int SRC, int DST>
__global__ __launch_bounds__(256) void feat_gemm(const float* __restrict__ Xext,
                                                 const float* __restrict__ W) {
    const float* X = (SRC == 0) ? Xext : (SRC == 1) ? (const float*)g_X1 : (const float*)g_X2;
    float* C = (DST == 0) ? (float*)g_Y : (float*)g_Wh;

    __shared__ float As[64][32];
    __shared__ float Bs[32][128];
    const int r0 = blockIdx.x * 64;
    const int rg = threadIdx.x >> 5;   // 0..7
    const int cg = threadIdx.x & 31;   // 0..31
    float acc[8][4] = {};

    for (int k0 = 0; k0 < 128; k0 += 32) {
        #pragma unroll
        for (int i = threadIdx.x; i < 512; i += 256) {
            int r = i >> 3, q = i & 7;
            *(float4*)&As[r][q*4] = *(const float4*)&X[(size_t)(r0 + r)*128 + k0 + q*4];
        }
        #pragma unroll
        for (int i = threadIdx.x; i < 1024; i += 256) {
            int r = i >> 5, q = i & 31;
            *(float4*)&Bs[r][q*4] = *(const float4*)&W[(k0 + r)*128 + q*4];
        }
        __syncthreads();
        #pragma unroll
        for (int kk = 0; kk < 32; kk++) {
            float4 bv = *(float4*)&Bs[kk][cg*4];
            #pragma unroll
            for (int r = 0; r < 8; r++) {
                float a = As[rg*8 + r][kk];
                acc[r][0] += a * bv.x; acc[r][1] += a * bv.y;
                acc[r][2] += a * bv.z; acc[r][3] += a * bv.w;
            }
        }
        __syncthreads();
    }
    #pragma unroll
    for (int r = 0; r < 8; r++) {
        float4 v = make_float4(acc[r][0], acc[r][1], acc[r][2], acc[r][3]);
        *(float4*)&C[(size_t)(r0 + rg*8 + r)*128 + cg*4] = v;
    }
}

// ============================================================================
// Adjacency GEMM: per batch b:  out = epilogue( adj[b](N x N) @ g_Y[b](N x 128) )
// MODE 0: g_X1 = relu(acc) * mask
// MODE 1: g_X2 = g_X1 + relu(acc) * mask
// ============================================================================
template<int MODE>
__global__ __launch_bounds__(256) void adj_gemm(const float* __restrict__ adj,
                                                const float* __restrict__ mask) {
    const int b  = blockIdx.y;
    const int r0 = blockIdx.x * 64;
    const float* A  = adj + (size_t)b*NN*NN;
    const float* Yb = (const float*)g_Y + (size_t)b*NN*HD;

    __shared__ float As[64][32];
    __shared__ float Bs[32][128];
    const int rg = threadIdx.x >> 5;
    const int cg = threadIdx.x & 31;
    float acc[8][4] = {};

    for (int k0 = 0; k0 < NN; k0 += 32) {
        #pragma unroll
        for (int i = threadIdx.x; i < 512; i += 256) {
            int r = i >> 3, q = i & 7;
            *(float4*)&As[r][q*4] = *(const float4*)&A[(size_t)(r0 + r)*NN + k0 + q*4];
        }
        #pragma unroll
        for (int i = threadIdx.x; i < 1024; i += 256) {
            int r = i >> 5, q = i & 31;
            *(float4*)&Bs[r][q*4] = *(const float4*)&Yb[(size_t)(k0 + r)*HD + q*4];
        }
        __syncthreads();
        #pragma unroll
        for (int kk = 0; kk < 32; kk++) {
            float4 bv = *(float4*)&Bs[kk][cg*4];
            #pragma unroll
            for (int r = 0; r < 8; r++) {
                float a = As[rg*8 + r][kk];
                acc[r][0] += a * bv.x; acc[r][1] += a * bv.y;
                acc[r][2] += a * bv.z; acc[r][3] += a * bv.w;
            }
        }
        __syncthreads();
    }
    #pragma unroll
    for (int r = 0; r < 8; r++) {
        int row = r0 + rg*8 + r;
        float mk = mask[b*NN + row];
        float4 v;
        v.x = fmaxf(acc[r][0], 0.f) * mk;
        v.y = fmaxf(acc[r][1], 0.f) * mk;
        v.z = fmaxf(acc[r][2], 0.f) * mk;
        v.w = fmaxf(acc[r][3], 0.f) * mk;
        size_t idx = (size_t)b*NN*HD + (size_t)row*HD + cg*4;
        if (MODE == 1) {
            float4 x = *(const float4*)&g_X1[idx];
            v.x += x.x; v.y += x.y; v.z += x.z; v.w += x.w;
            *(float4*)&g_X2[idx] = v;
        } else {
            *(float4*)&g_X1[idx] = v;
        }
    }
}

// ============================================================================
// s1/s2: per-row dots of g_Wh with a1 = a[0:128], a2 = a[128:256]
// One warp per row.
// ============================================================================
__global__ __launch_bounds__(256) void s12_kernel(const float* __restrict__ a) {
    int row  = blockIdx.x * 8 + (threadIdx.x >> 5);
    int lane = threadIdx.x & 31;
    float4 x  = *(const float4*)&g_Wh[(size_t)row*128 + lane*4];
    float4 a1 = *(const float4*)&a[lane*4];
    float4 a2 = *(const float4*)&a[128 + lane*4];
    float d1 = x.x*a1.x + x.y*a1.y + x.z*a1.z + x.w*a1.w;
    float d2 = x.x*a2.x + x.y*a2.y + x.z*a2.z + x.w*a2.w;
    #pragma unroll
    for (int off = 16; off > 0; off >>= 1) {
        d1 += __shfl_xor_sync(0xffffffffu, d1, off);
        d2 += __shfl_xor_sync(0xffffffffu, d2, off);
    }
    if (lane == 0) { g_s1[row] = d1; g_s2[row] = d2; }
}

// ============================================================================
// GAT: flash-attention style online softmax over masked e[i,j] = lrelu(s1_i+s2_j)
// then x3 = relu(attn @ Wh) * mask. Tile: 64 query rows, j-tiles of 32.
// ============================================================================
__global__ __launch_bounds__(256) void gat_kernel(const float* __restrict__ adj,
                                                  const float* __restrict__ mask) {
    const int b  = blockIdx.y;
    const int i0 = blockIdx.x * 64;
    const float* Ab  = adj + (size_t)b*NN*NN;
    const float* Whb = (const float*)g_Wh + (size_t)b*NN*HD;

    __shared__ float Whs[32][128];
    __shared__ float Ps[64][32];
    __shared__ float s2s[32], nms[32];
    __shared__ float scaleS[64], lS[64], s1S[64], nmiS[64];

    const int tid  = threadIdx.x;
    const int rg   = tid >> 5, cg = tid & 31;
    const int prow = tid >> 2, psub = tid & 3;

    if (tid < 64) {
        s1S[tid]  = g_s1[b*NN + i0 + tid];
        nmiS[tid] = mask[b*NN + i0 + tid];
    }

    float acc[8][4] = {};
    float m = -INFINITY, l = 0.f;

    for (int j0 = 0; j0 < NN; j0 += 32) {
        __syncthreads();  // previous gemm done reading Ps/Whs
        #pragma unroll
        for (int i = tid; i < 1024; i += 256) {
            int r = i >> 5, q = i & 31;
            *(float4*)&Whs[r][q*4] = *(const float4*)&Whb[(size_t)(j0 + r)*HD + q*4];
        }
        if (tid < 32) {
            s2s[tid] = g_s2[b*NN + j0 + tid];
            nms[tid] = mask[b*NN + j0 + tid];
        }
        __syncthreads();  // smem visible

        // --- p computation: 4 threads/row, 8 cols each ---
        float s1v = s1S[prow], nmi = nmiS[prow];
        const float* arow = Ab + (size_t)(i0 + prow)*NN + j0 + psub*8;
        float4 a0 = *(const float4*)&arow[0];
        float4 a1 = *(const float4*)&arow[4];
        float av[8] = {a0.x, a0.y, a0.z, a0.w, a1.x, a1.y, a1.z, a1.w};
        float vals[8];
        float tmax = -INFINITY;
        #pragma unroll
        for (int jj = 0; jj < 8; jj++) {
            int jl = psub*8 + jj;
            float e = s1v + s2s[jl];
            e = (e > 0.f) ? e : ALPHAV * e;
            float edge = (av[jj] > 0.f) ? (nms[jl] * nmi) : 0.f;
            float v = (edge > 0.f) ? e : NEGV;
            vals[jj] = v;
            tmax = fmaxf(tmax, v);
        }
        tmax = fmaxf(tmax, __shfl_xor_sync(0xffffffffu, tmax, 1));
        tmax = fmaxf(tmax, __shfl_xor_sync(0xffffffffu, tmax, 2));
        float mn    = fmaxf(m, tmax);
        float scale = __expf(m - mn);
        float psum = 0.f;
        #pragma unroll
        for (int jj = 0; jj < 8; jj++) {
            float p = __expf(vals[jj] - mn);
            Ps[prow][psub*8 + jj] = p;
            psum += p;
        }
        psum += __shfl_xor_sync(0xffffffffu, psum, 1);
        psum += __shfl_xor_sync(0xffffffffu, psum, 2);
        l = l * scale + psum;
        m = mn;
        if (psub == 0) scaleS[prow] = scale;
        __syncthreads();  // Ps/scale visible

        // --- rescale accumulators + P @ Wh ---
        #pragma unroll
        for (int r = 0; r < 8; r++) {
            float s = scaleS[rg*8 + r];
            acc[r][0] *= s; acc[r][1] *= s; acc[r][2] *= s; acc[r][3] *= s;
        }
        #pragma unroll
        for (int kk = 0; kk < 32; kk++) {
            float4 bv = *(float4*)&Whs[kk][cg*4];
            #pragma unroll
            for (int r = 0; r < 8; r++) {
                float p = Ps[rg*8 + r][kk];
                acc[r][0] += p * bv.x; acc[r][1] += p * bv.y;
                acc[r][2] += p * bv.z; acc[r][3] += p * bv.w;
            }
        }
    }
    if (psub == 0) lS[prow] = l;
    __syncthreads();

    float* x3b = (float*)g_x3 + (size_t)b*NN*HD;
    #pragma unroll
    for (int r = 0; r < 8; r++) {
        int row = rg*8 + r;
        float inv = 1.f / lS[row];
        float nmi = nmiS[row];
        float4 v;
        v.x = fmaxf(acc[r][0]*inv, 0.f) * nmi;
        v.y = fmaxf(acc[r][1]*inv, 0.f) * nmi;
        v.z = fmaxf(acc[r][2]*inv, 0.f) * nmi;
        v.w = fmaxf(acc[r][3]*inv, 0.f) * nmi;
        *(float4*)&x3b[(size_t)(i0 + row)*HD + cg*4] = v;
    }
}

// ============================================================================
// soft attention: satt = sigmoid(x3 . w_sa + b_sa), one warp per row
// ============================================================================
__global__ __launch_bounds__(256) void satt_kernel(const float* __restrict__ w_sa,
                                                   const float* __restrict__ b_sa) {
    int row  = blockIdx.x * 8 + (threadIdx.x >> 5);
    int lane = threadIdx.x & 31;
    float4 x = *(const float4*)&g_x3[(size_t)row*128 + lane*4];
    float4 w = *(const float4*)&w_sa[lane*4];
    float d = x.x*w.x + x.y*w.y + x.z*w.z + x.w*w.w;
    #pragma unroll
    for (int off = 16; off > 0; off >>= 1)
        d += __shfl_xor_sync(0xffffffffu, d, off);
    if (lane == 0) {
        float z = d + b_sa[0];
        g_satt[row] = 1.f / (1.f + __expf(-z));
    }
}

// ============================================================================
// Final layer: x = satt * relu(x3 @ W_ln + b_ln) * mask, with per-tile
// partial sum & max over the 64-row tile written to g_psum/g_pmax.
// ============================================================================
__global__ __launch_bounds__(256) void final_gemm(const float* __restrict__ Wln,
                                                  const float* __restrict__ bln,
                                                  const float* __restrict__ mask) {
    __shared__ float As[64][32];
    __shared__ float Bs[32][128];
    __shared__ float redS[8][128];
    __shared__ float redM[8][128];
    const int r0 = blockIdx.x * 64;
    const int rg = threadIdx.x >> 5;
    const int cg = threadIdx.x & 31;
    float acc[8][4] = {};

    for (int k0 = 0; k0 < 128; k0 += 32) {
        #pragma unroll
        for (int i = threadIdx.x; i < 512; i += 256) {
            int r = i >> 3, q = i & 7;
            *(float4*)&As[r][q*4] = *(const float4*)&g_x3[(size_t)(r0 + r)*128 + k0 + q*4];
        }
        #pragma unroll
        for (int i = threadIdx.x; i < 1024; i += 256) {
            int r = i >> 5, q = i & 31;
            *(float4*)&Bs[r][q*4] = *(const float4*)&Wln[(k0 + r)*128 + q*4];
        }
        __syncthreads();
        #pragma unroll
        for (int kk = 0; kk < 32; kk++) {
            float4 bv = *(float4*)&Bs[kk][cg*4];
            #pragma unroll
            for (int r = 0; r < 8; r++) {
                float a = As[rg*8 + r][kk];
                acc[r][0] += a * bv.x; acc[r][1] += a * bv.y;
                acc[r][2] += a * bv.z; acc[r][3] += a * bv.w;
            }
        }
        __syncthreads();
    }

    float4 bl = *(const float4*)&bln[cg*4];
    float s[4]  = {0.f, 0.f, 0.f, 0.f};
    float mx[4] = {-INFINITY, -INFINITY, -INFINITY, -INFINITY};
    #pragma unroll
    for (int r = 0; r < 8; r++) {
        int row = r0 + rg*8 + r;
        float sa = g_satt[row] * mask[row];
        float v0 = fmaxf(acc[r][0] + bl.x, 0.f) * sa;
        float v1 = fmaxf(acc[r][1] + bl.y, 0.f) * sa;
        float v2 = fmaxf(acc[r][2] + bl.z, 0.f) * sa;
        float v3 = fmaxf(acc[r][3] + bl.w, 0.f) * sa;
        s[0] += v0; s[1] += v1; s[2] += v2; s[3] += v3;
        mx[0] = fmaxf(mx[0], v0); mx[1] = fmaxf(mx[1], v1);
        mx[2] = fmaxf(mx[2], v2); mx[3] = fmaxf(mx[3], v3);
    }
    #pragma unroll
    for (int c = 0; c < 4; c++) {
        redS[rg][cg*4 + c] = s[c];
        redM[rg][cg*4 + c] = mx[c];
    }
    __syncthreads();
    if (threadIdx.x < 32) {
        int bI = r0 >> 10;
        int t  = (r0 >> 6) & 15;
        #pragma unroll
        for (int c = 0; c < 4; c++) {
            int col = threadIdx.x*4 + c;
            float ss = 0.f, mm = -INFINITY;
            #pragma unroll
            for (int g = 0; g < 8; g++) {
                ss += redS[g][col];
                mm = fmaxf(mm, redM[g][col]);
            }
            g_psum[(bI*16 + t)*HD + col] = ss;
            g_pmax[(bI*16 + t)*HD + col] = mm;
        }
    }
}

__global__ void final_reduce(float* __restrict__ out) {
    int b = blockIdx.x, h = threadIdx.x;
    float s = 0.f, mx = -INFINITY;
    #pragma unroll
    for (int t = 0; t < 16; t++) {
        s += g_psum[(b*16 + t)*HD + h];
        mx = fmaxf(mx, g_pmax[(b*16 + t)*HD + h]);
    }
    out[b*HD + h] = s * mx;
}

// ============================================================================
extern "C" void kernel_launch(void* const* d_in, const int* in_sizes, int n_in,
                              void* d_out, int out_size) {
    const float* inputs = (const float*)d_in[0];
    const float* adj    = (const float*)d_in[1];
    const float* mask   = (const float*)d_in[2];
    const float* W0     = (const float*)d_in[3];
    const float* W1     = (const float*)d_in[4];
    const float* Wg     = (const float*)d_in[5];
    const float* a      = (const float*)d_in[6];
    const float* w_sa   = (const float*)d_in[7];
    const float* b_sa   = (const float*)d_in[8];
    const float* W_ln   = (const float*)d_in[9];
    const float* b_ln   = (const float*)d_in[10];
    float* out = (float*)d_out;

    const int ROWS = BB * NN;               // 16384
    dim3 gFeat(ROWS / 64);                  // 256
    dim3 gAdj(NN / 64, BB);                 // (16,16)
    dim3 gWarp(ROWS / 8);                   // 2048 (one warp/row, 8 warps/block)

    // x1 = relu(adj @ (inputs @ W0)) * mask
    feat_gemm<0, 0><<<gFeat, 256>>>(inputs, W0);
    adj_gemm<0><<<gAdj, 256>>>(adj, mask);
    // x2 = x1 + relu(adj @ (x1 @ W1)) * mask
    feat_gemm<1, 0><<<gFeat, 256>>>(nullptr, W1);
    adj_gemm<1><<<gAdj, 256>>>(adj, mask);
    // GAT
    feat_gemm<2, 1><<<gFeat, 256>>>(nullptr, Wg);   // Wh = x2 @ Wg
    s12_kernel<<<gWarp, 256>>>(a);
    gat_kernel<<<gAdj, 256>>>(adj, mask);
    // epilogue
    satt_kernel<<<gWarp, 256>>>(w_sa, b_sa);
    final_gemm<<<gFeat, 256>>>(W_ln, b_ln, mask);
    final_reduce<<<BB, HD>>>(out);
}

// round 2
// speedup vs baseline: 1.7372x; 1.7372x over previous
#include <cuda_runtime.h>
#include <math.h>

#define BB 16
#define NN 1024
#define HD 128
#define NEGV (-9000000000000000.0f)
#define ALPHAV 0.2f

// ---------------- scratch (device globals; no allocation allowed) ----------------
__device__ float g_Y [BB*NN*HD];
__device__ float g_X1[BB*NN*HD];
__device__ float g_X2[BB*NN*HD];
__device__ float g_Wh[BB*NN*HD];
__device__ float g_x3[BB*NN*HD];
__device__ float g_s1[BB*NN];
__device__ float g_s2[BB*NN];
__device__ float g_satt[BB*NN];
__device__ float g_psum[BB*16*HD];
__device__ float g_pmax[BB*16*HD];

// ---------------- PTX helpers ----------------
__device__ __forceinline__ unsigned smem_u32(const void* p) {
    return (unsigned)__cvta_generic_to_shared(p);
}
__device__ __forceinline__ void cpa16(void* s, const void* g) {
    asm volatile("cp.async.cg.shared.global [%0], [%1], 16;" :: "r"(smem_u32(s)), "l"(g));
}
__device__ __forceinline__ void cpa_commit() { asm volatile("cp.async.commit_group;"); }
template<int N>
__device__ __forceinline__ void cpa_wait() { asm volatile("cp.async.wait_group %0;" :: "n"(N)); }
__device__ __forceinline__ unsigned f2tf(float f) {
    unsigned u; asm("cvt.rna.tf32.f32 %0, %1;" : "=r"(u) : "f"(f)); return u;
}
__device__ __forceinline__ void mma_tf32(float* c, const unsigned* a, const unsigned* b) {
    asm volatile(
        "mma.sync.aligned.m16n8k8.row.col.f32.tf32.tf32.f32 "
        "{%0,%1,%2,%3}, {%4,%5,%6,%7}, {%8,%9}, {%0,%1,%2,%3};"
        : "+f"(c[0]), "+f"(c[1]), "+f"(c[2]), "+f"(c[3])
        : "r"(a[0]), "r"(a[1]), "r"(a[2]), "r"(a[3]), "r"(b[0]), "r"(b[1]));
}

// ============================================================================
// Feature GEMM (fp32 SIMT, kept for accuracy): C = X @ W, 16384x128x128
// ============================================================================
template<int SRC, int DST>
__global__ __launch_bounds__(256) void feat_gemm(const float* __restrict__ Xext,
                                                 const float* __restrict__ W) {
    const float* X = (SRC == 0) ? Xext : (SRC == 1) ? (const float*)g_X1 : (const float*)g_X2;
    float* C = (DST == 0) ? (float*)g_Y : (float*)g_Wh;

    __shared__ float As[64][32];
    __shared__ float Bs[32][128];
    const int r0 = blockIdx.x * 64;
    const int rg = threadIdx.x >> 5;
    const int cg = threadIdx.x & 31;
    float acc[8][4] = {};

    for (int k0 = 0; k0 < 128; k0 += 32) {
        #pragma unroll
        for (int i = threadIdx.x; i < 512; i += 256) {
            int r = i >> 3, q = i & 7;
            *(float4*)&As[r][q*4] = *(const float4*)&X[(size_t)(r0 + r)*128 + k0 + q*4];
        }
        #pragma unroll
        for (int i = threadIdx.x; i < 1024; i += 256) {
            int r = i >> 5, q = i & 31;
            *(float4*)&Bs[r][q*4] = *(const float4*)&W[(k0 + r)*128 + q*4];
        }
        __syncthreads();
        #pragma unroll
        for (int kk = 0; kk < 32; kk++) {
            float4 bv = *(float4*)&Bs[kk][cg*4];
            #pragma unroll
            for (int r = 0; r < 8; r++) {
                float a = As[rg*8 + r][kk];
                acc[r][0] += a * bv.x; acc[r][1] += a * bv.y;
                acc[r][2] += a * bv.z; acc[r][3] += a * bv.w;
            }
        }
        __syncthreads();
    }
    #pragma unroll
    for (int r = 0; r < 8; r++) {
        float4 v = make_float4(acc[r][0], acc[r][1], acc[r][2], acc[r][3]);
        *(float4*)&C[(size_t)(r0 + rg*8 + r)*128 + cg*4] = v;
    }
}

// ============================================================================
// Adjacency GEMM on tensor cores (tf32):
//   per batch: epilogue( adj[b](1024x1024) @ g_Y[b](1024x128) )
// CTA tile 128x128, BK=32, cp.async double-buffered. 8 warps, warp tile 32x64.
// MODE 0: g_X1 = relu(acc)*mask ; MODE 1: g_X2 = g_X1 + relu(acc)*mask
// ============================================================================
#define ADJ_SMEM_BYTES (2*128*36*4 + 2*32*136*4)

template<int MODE>
__global__ __launch_bounds__(256) void adj_gemm_tc(const float* __restrict__ adj,
                                                   const float* __restrict__ mask) {
    extern __shared__ char dynsm[];
    float (*As)[128][36] = reinterpret_cast<float(*)[128][36]>(dynsm);
    float (*Bs)[32][136] = reinterpret_cast<float(*)[32][136]>(dynsm + 2*128*36*4);

    const int b  = blockIdx.y;
    const int r0 = blockIdx.x * 128;
    const float* A  = adj + (size_t)b*NN*NN;
    const float* Yb = (const float*)g_Y + (size_t)b*NN*HD;
    const int tid = threadIdx.x;

    auto load_stage = [&](int st, int k0) {
        #pragma unroll
        for (int i = tid; i < 1024; i += 256) {
            int r = i >> 3, q = i & 7;
            cpa16(&As[st][r][q*4], &A[(size_t)(r0 + r)*NN + k0 + q*4]);
        }
        #pragma unroll
        for (int i = tid; i < 1024; i += 256) {
            int r = i >> 5, q = i & 31;
            cpa16(&Bs[st][r][q*4], &Yb[(size_t)(k0 + r)*HD + q*4]);
        }
        cpa_commit();
    };

    load_stage(0, 0);

    const int warp = tid >> 5, lane = tid & 31;
    const int wr = (warp >> 1) * 32;     // warp row offset in tile
    const int wc = (warp & 1) * 64;      // warp col offset
    const int lr = lane >> 2;            // 0..7
    const int lc = lane & 3;             // 0..3

    float acc[2][8][4];
    #pragma unroll
    for (int m = 0; m < 2; m++)
        #pragma unroll
        for (int n = 0; n < 8; n++)
            #pragma unroll
            for (int q = 0; q < 4; q++) acc[m][n][q] = 0.f;

    for (int kt = 0; kt < 32; kt++) {
        const int cur = kt & 1;
        if (kt + 1 < 32) { load_stage(cur ^ 1, (kt + 1) * 32); cpa_wait<1>(); }
        else             { cpa_wait<0>(); }
        __syncthreads();

        #pragma unroll
        for (int ks = 0; ks < 32; ks += 8) {
            unsigned af[2][4];
            #pragma unroll
            for (int m = 0; m < 2; m++) {
                int r = wr + m*16 + lr;
                af[m][0] = f2tf(As[cur][r    ][ks + lc    ]);
                af[m][1] = f2tf(As[cur][r + 8][ks + lc    ]);
                af[m][2] = f2tf(As[cur][r    ][ks + lc + 4]);
                af[m][3] = f2tf(As[cur][r + 8][ks + lc + 4]);
            }
            unsigned bf[8][2];
            #pragma unroll
            for (int n = 0; n < 8; n++) {
                int c = wc + n*8 + lr;
                bf[n][0] = f2tf(Bs[cur][ks + lc    ][c]);
                bf[n][1] = f2tf(Bs[cur][ks + lc + 4][c]);
            }
            #pragma unroll
            for (int m = 0; m < 2; m++)
                #pragma unroll
                for (int n = 0; n < 8; n++)
                    mma_tf32(acc[m][n], af[m], bf[n]);
        }
        __syncthreads();
    }

    #pragma unroll
    for (int m = 0; m < 2; m++) {
        #pragma unroll
        for (int half = 0; half < 2; half++) {
            int row = r0 + wr + m*16 + lr + half*8;
            float mk = mask[b*NN + row];
            size_t base = (size_t)b*NN*HD + (size_t)row*HD;
            #pragma unroll
            for (int n = 0; n < 8; n++) {
                int col = wc + n*8 + 2*lc;
                float v0 = fmaxf(acc[m][n][half*2 + 0], 0.f) * mk;
                float v1 = fmaxf(acc[m][n][half*2 + 1], 0.f) * mk;
                if (MODE == 1) {
                    float2 x = *(const float2*)&g_X1[base + col];
                    v0 += x.x; v1 += x.y;
                    *(float2*)&g_X2[base + col] = make_float2(v0, v1);
                } else {
                    *(float2*)&g_X1[base + col] = make_float2(v0, v1);
                }
            }
        }
    }
}

// ============================================================================
// s1/s2 per-row dots
// ============================================================================
__global__ __launch_bounds__(256) void s12_kernel(const float* __restrict__ a) {
    int row  = blockIdx.x * 8 + (threadIdx.x >> 5);
    int lane = threadIdx.x & 31;
    float4 x  = *(const float4*)&g_Wh[(size_t)row*128 + lane*4];
    float4 a1 = *(const float4*)&a[lane*4];
    float4 a2 = *(const float4*)&a[128 + lane*4];
    float d1 = x.x*a1.x + x.y*a1.y + x.z*a1.z + x.w*a1.w;
    float d2 = x.x*a2.x + x.y*a2.y + x.z*a2.z + x.w*a2.w;
    #pragma unroll
    for (int off = 16; off > 0; off >>= 1) {
        d1 += __shfl_xor_sync(0xffffffffu, d1, off);
        d2 += __shfl_xor_sync(0xffffffffu, d2, off);
    }
    if (lane == 0) { g_s1[row] = d1; g_s2[row] = d2; }
}

// ============================================================================
// GAT: online-softmax flash attention; P@Wh on tensor cores.
// 64 query rows per CTA, j-tiles of 32. 8 warps, warp tile 16x64 for the mma.
// ============================================================================
__global__ __launch_bounds__(256) void gat_tc(const float* __restrict__ adj,
                                              const float* __restrict__ mask) {
    const int b  = blockIdx.y;
    const int i0 = blockIdx.x * 64;
    const float* Ab  = adj + (size_t)b*NN*NN;
    const float* Whb = (const float*)g_Wh + (size_t)b*NN*HD;

    __shared__ float Whs[2][32][136];   // 34816 B
    __shared__ float Ps[64][36];        //  9216 B
    __shared__ float scaleS[64], lS[64], s1S[64], nmiS[64];

    const int tid  = threadIdx.x;
    const int warp = tid >> 5, lane = tid & 31;
    const int m0   = (warp >> 1) * 16;
    const int wc   = (warp & 1) * 64;
    const int lr   = lane >> 2, lc = lane & 3;
    const int prow = tid >> 2, psub = tid & 3;

    if (tid < 64) {
        s1S[tid]  = g_s1[b*NN + i0 + tid];
        nmiS[tid] = mask[b*NN + i0 + tid];
    }

    auto load_wh = [&](int st, int j0) {
        #pragma unroll
        for (int i = tid; i < 1024; i += 256) {
            int r = i >> 5, q = i & 31;
            cpa16(&Whs[st][r][q*4], &Whb[(size_t)(j0 + r)*HD + q*4]);
        }
        cpa_commit();
    };

    load_wh(0, 0);

    // adj prefetch regs for current j-tile (4 threads/row, 8 cols each)
    const float* arow_base = Ab + (size_t)(i0 + prow)*NN + psub*8;
    float4 pa0 = *(const float4*)&arow_base[0];
    float4 pa1 = *(const float4*)&arow_base[4];

    float acc[8][4];
    #pragma unroll
    for (int n = 0; n < 8; n++)
        #pragma unroll
        for (int q = 0; q < 4; q++) acc[n][q] = 0.f;

    float m = -INFINITY, l = 0.f;
    __syncthreads();   // s1S/nmiS visible

    for (int jt = 0; jt < 32; jt++) {
        const int cur = jt & 1;
        const int j0  = jt * 32;
        if (jt + 1 < 32) load_wh(cur ^ 1, j0 + 32);

        // ---- softmax phase (SIMT) ----
        float s1v = s1S[prow], nmi = nmiS[prow];
        float4 s2a = *(const float4*)&g_s2[b*NN + j0 + psub*8];
        float4 s2b = *(const float4*)&g_s2[b*NN + j0 + psub*8 + 4];
        float4 nma = *(const float4*)&mask[b*NN + j0 + psub*8];
        float4 nmb = *(const float4*)&mask[b*NN + j0 + psub*8 + 4];
        float s2v[8] = {s2a.x, s2a.y, s2a.z, s2a.w, s2b.x, s2b.y, s2b.z, s2b.w};
        float nmv[8] = {nma.x, nma.y, nma.z, nma.w, nmb.x, nmb.y, nmb.z, nmb.w};
        float av[8]  = {pa0.x, pa0.y, pa0.z, pa0.w, pa1.x, pa1.y, pa1.z, pa1.w};

        float vals[8];
        float tmax = -INFINITY;
        #pragma unroll
        for (int jj = 0; jj < 8; jj++) {
            float e = s1v + s2v[jj];
            e = (e > 0.f) ? e : ALPHAV * e;
            float edge = (av[jj] > 0.f) ? (nmv[jj] * nmi) : 0.f;
            float v = (edge > 0.f) ? e : NEGV;
            vals[jj] = v;
            tmax = fmaxf(tmax, v);
        }
        tmax = fmaxf(tmax, __shfl_xor_sync(0xffffffffu, tmax, 1));
        tmax = fmaxf(tmax, __shfl_xor_sync(0xffffffffu, tmax, 2));
        float mn    = fmaxf(m, tmax);
        float scale = __expf(m - mn);
        float psum = 0.f;
        #pragma unroll
        for (int jj = 0; jj < 8; jj++) {
            float p = __expf(vals[jj] - mn);
            float pr = __uint_as_float(f2tf(p));   // round to tf32; use rounded in BOTH l and P@Wh
            Ps[prow][psub*8 + jj] = pr;
            psum += pr;
        }
        psum += __shfl_xor_sync(0xffffffffu, psum, 1);
        psum += __shfl_xor_sync(0xffffffffu, psum, 2);
        l = l * scale + psum;
        m = mn;
        if (psub == 0) scaleS[prow] = scale;

        // prefetch adj for next tile (overlaps with mma below)
        if (jt + 1 < 32) {
            pa0 = *(const float4*)&arow_base[j0 + 32];
            pa1 = *(const float4*)&arow_base[j0 + 36];
        }

        if (jt + 1 < 32) cpa_wait<1>(); else cpa_wait<0>();
        __syncthreads();   // Ps, scaleS, Whs[cur] ready

        // ---- rescale + P @ Wh (tensor cores) ----
        float sc0 = scaleS[m0 + lr], sc1 = scaleS[m0 + lr + 8];
        #pragma unroll
        for (int n = 0; n < 8; n++) {
            acc[n][0] *= sc0; acc[n][1] *= sc0;
            acc[n][2] *= sc1; acc[n][3] *= sc1;
        }
        #pragma unroll
        for (int ks = 0; ks < 32; ks += 8) {
            unsigned af[4];
            af[0] = f2tf(Ps[m0 + lr    ][ks + lc    ]);
            af[1] = f2tf(Ps[m0 + lr + 8][ks + lc    ]);
            af[2] = f2tf(Ps[m0 + lr    ][ks + lc + 4]);
            af[3] = f2tf(Ps[m0 + lr + 8][ks + lc + 4]);
            unsigned bf[8][2];
            #pragma unroll
            for (int n = 0; n < 8; n++) {
                int c = wc + n*8 + lr;
                bf[n][0] = f2tf(Whs[cur][ks + lc    ][c]);
                bf[n][1] = f2tf(Whs[cur][ks + lc + 4][c]);
            }
            #pragma unroll
            for (int n = 0; n < 8; n++)
                mma_tf32(acc[n], af, bf[n]);
        }
        __syncthreads();   // all warps done with Ps/Whs[cur] before overwrite
    }

    if (psub == 0) lS[prow] = l;
    __syncthreads();

    float* x3b = (float*)g_x3 + (size_t)b*NN*HD;
    #pragma unroll
    for (int half = 0; half < 2; half++) {
        int rloc = m0 + lr + half*8;
        float inv = 1.f / lS[rloc];
        float nmi = nmiS[rloc];
        size_t base = (size_t)(i0 + rloc)*HD;
        #pragma unroll
        for (int n = 0; n < 8; n++) {
            int col = wc + n*8 + 2*lc;
            float v0 = fmaxf(acc[n][half*2 + 0]*inv, 0.f) * nmi;
            float v1 = fmaxf(acc[n][half*2 + 1]*inv, 0.f) * nmi;
            *(float2*)&x3b[base + col] = make_float2(v0, v1);
        }
    }
}

// ============================================================================
// soft attention sigmoid
// ============================================================================
__global__ __launch_bounds__(256) void satt_kernel(const float* __restrict__ w_sa,
                                                   const float* __restrict__ b_sa) {
    int row  = blockIdx.x * 8 + (threadIdx.x >> 5);
    int lane = threadIdx.x & 31;
    float4 x = *(const float4*)&g_x3[(size_t)row*128 + lane*4];
    float4 w = *(const float4*)&w_sa[lane*4];
    float d = x.x*w.x + x.y*w.y + x.z*w.z + x.w*w.w;
    #pragma unroll
    for (int off = 16; off > 0; off >>= 1)
        d += __shfl_xor_sync(0xffffffffu, d, off);
    if (lane == 0) {
        float z = d + b_sa[0];
        g_satt[row] = 1.f / (1.f + __expf(-z));
    }
}

// ============================================================================
// Final layer + per-tile partial sum/max
// ============================================================================
__global__ __launch_bounds__(256) void final_gemm(const float* __restrict__ Wln,
                                                  const float* __restrict__ bln,
                                                  const float* __restrict__ mask) {
    __shared__ float As[64][32];
    __shared__ float Bs[32][128];
    __shared__ float redS[8][128];
    __shared__ float redM[8][128];
    const int r0 = blockIdx.x * 64;
    const int rg = threadIdx.x >> 5;
    const int cg = threadIdx.x & 31;
    float acc[8][4] = {};

    for (int k0 = 0; k0 < 128; k0 += 32) {
        #pragma unroll
        for (int i = threadIdx.x; i < 512; i += 256) {
            int r = i >> 3, q = i & 7;
            *(float4*)&As[r][q*4] = *(const float4*)&g_x3[(size_t)(r0 + r)*128 + k0 + q*4];
        }
        #pragma unroll
        for (int i = threadIdx.x; i < 1024; i += 256) {
            int r = i >> 5, q = i & 31;
            *(float4*)&Bs[r][q*4] = *(const float4*)&Wln[(k0 + r)*128 + q*4];
        }
        __syncthreads();
        #pragma unroll
        for (int kk = 0; kk < 32; kk++) {
            float4 bv = *(float4*)&Bs[kk][cg*4];
            #pragma unroll
            for (int r = 0; r < 8; r++) {
                float a = As[rg*8 + r][kk];
                acc[r][0] += a * bv.x; acc[r][1] += a * bv.y;
                acc[r][2] += a * bv.z; acc[r][3] += a * bv.w;
            }
        }
        __syncthreads();
    }

    float4 bl = *(const float4*)&bln[cg*4];
    float s[4]  = {0.f, 0.f, 0.f, 0.f};
    float mx[4] = {-INFINITY, -INFINITY, -INFINITY, -INFINITY};
    #pragma unroll
    for (int r = 0; r < 8; r++) {
        int row = r0 + rg*8 + r;
        float sa = g_satt[row] * mask[row];
        float v0 = fmaxf(acc[r][0] + bl.x, 0.f) * sa;
        float v1 = fmaxf(acc[r][1] + bl.y, 0.f) * sa;
        float v2 = fmaxf(acc[r][2] + bl.z, 0.f) * sa;
        float v3 = fmaxf(acc[r][3] + bl.w, 0.f) * sa;
        s[0] += v0; s[1] += v1; s[2] += v2; s[3] += v3;
        mx[0] = fmaxf(mx[0], v0); mx[1] = fmaxf(mx[1], v1);
        mx[2] = fmaxf(mx[2], v2); mx[3] = fmaxf(mx[3], v3);
    }
    #pragma unroll
    for (int c = 0; c < 4; c++) {
        redS[rg][cg*4 + c] = s[c];
        redM[rg][cg*4 + c] = mx[c];
    }
    __syncthreads();
    if (threadIdx.x < 32) {
        int bI = r0 >> 10;
        int t  = (r0 >> 6) & 15;
        #pragma unroll
        for (int c = 0; c < 4; c++) {
            int col = threadIdx.x*4 + c;
            float ss = 0.f, mm = -INFINITY;
            #pragma unroll
            for (int g = 0; g < 8; g++) {
                ss += redS[g][col];
                mm = fmaxf(mm, redM[g][col]);
            }
            g_psum[(bI*16 + t)*HD + col] = ss;
            g_pmax[(bI*16 + t)*HD + col] = mm;
        }
    }
}

__global__ void final_reduce(float* __restrict__ out) {
    int b = blockIdx.x, h = threadIdx.x;
    float s = 0.f, mx = -INFINITY;
    #pragma unroll
    for (int t = 0; t < 16; t++) {
        s += g_psum[(b*16 + t)*HD + h];
        mx = fmaxf(mx, g_pmax[(b*16 + t)*HD + h]);
    }
    out[b*HD + h] = s * mx;
}

// ============================================================================
extern "C" void kernel_launch(void* const* d_in, const int* in_sizes, int n_in,
                              void* d_out, int out_size) {
    const float* inputs = (const float*)d_in[0];
    const float* adj    = (const float*)d_in[1];
    const float* mask   = (const float*)d_in[2];
    const float* W0     = (const float*)d_in[3];
    const float* W1     = (const float*)d_in[4];
    const float* Wg     = (const float*)d_in[5];
    const float* a      = (const float*)d_in[6];
    const float* w_sa   = (const float*)d_in[7];
    const float* b_sa   = (const float*)d_in[8];
    const float* W_ln   = (const float*)d_in[9];
    const float* b_ln   = (const float*)d_in[10];
    float* out = (float*)d_out;

    cudaFuncSetAttribute(adj_gemm_tc<0>, cudaFuncAttributeMaxDynamicSharedMemorySize, ADJ_SMEM_BYTES);
    cudaFuncSetAttribute(adj_gemm_tc<1>, cudaFuncAttributeMaxDynamicSharedMemorySize, ADJ_SMEM_BYTES);

    const int ROWS = BB * NN;               // 16384
    dim3 gFeat(ROWS / 64);                  // 256
    dim3 gAdjTC(NN / 128, BB);              // (8,16)
    dim3 gGat(NN / 64, BB);                 // (16,16)
    dim3 gWarp(ROWS / 8);                   // 2048

    // x1 = relu(adj @ (inputs @ W0)) * mask
    feat_gemm<0, 0><<<gFeat, 256>>>(inputs, W0);
    adj_gemm_tc<0><<<gAdjTC, 256, ADJ_SMEM_BYTES>>>(adj, mask);
    // x2 = x1 + relu(adj @ (x1 @ W1)) * mask
    feat_gemm<1, 0><<<gFeat, 256>>>(nullptr, W1);
    adj_gemm_tc<1><<<gAdjTC, 256, ADJ_SMEM_BYTES>>>(adj, mask);
    // GAT
    feat_gemm<2, 1><<<gFeat, 256>>>(nullptr, Wg);   // Wh = x2 @ Wg
    s12_kernel<<<gWarp, 256>>>(a);
    gat_tc<<<gGat, 256>>>(adj, mask);
    // epilogue
    satt_kernel<<<gWarp, 256>>>(w_sa, b_sa);
    final_gemm<<<gFeat, 256>>>(W_ln, b_ln, mask);
    final_reduce<<<BB, HD>>>(out);
}

// round 3
// speedup vs baseline: 1.8066x; 1.0399x over previous
#include <cuda_runtime.h>
#include <math.h>

#define BB 16
#define NN 1024
#define HD 128
#define NEGV (-9000000000000000.0f)
#define ALPHAV 0.2f

// ---------------- scratch (device globals; no allocation allowed) ----------------
__device__ float g_Y [BB*NN*HD];
__device__ float g_X1[BB*NN*HD];
__device__ float g_X2[BB*NN*HD];
__device__ float g_Wh[BB*NN*HD];
__device__ float g_x3[BB*NN*HD];
__device__ float g_s1[BB*NN];
__device__ float g_s2[BB*NN];
__device__ float g_satt[BB*NN];
__device__ float g_psum[BB*16*HD];
__device__ float g_pmax[BB*16*HD];

// ---------------- PTX helpers ----------------
__device__ __forceinline__ unsigned smem_u32(const void* p) {
    return (unsigned)__cvta_generic_to_shared(p);
}
__device__ __forceinline__ void cpa16(void* s, const void* g) {
    asm volatile("cp.async.cg.shared.global [%0], [%1], 16;" :: "r"(smem_u32(s)), "l"(g));
}
__device__ __forceinline__ void cpa_commit() { asm volatile("cp.async.commit_group;"); }
template<int N>
__device__ __forceinline__ void cpa_wait() { asm volatile("cp.async.wait_group %0;" :: "n"(N)); }
__device__ __forceinline__ unsigned f2tf(float f) {
    unsigned u; asm("cvt.rna.tf32.f32 %0, %1;" : "=r"(u) : "f"(f)); return u;
}
__device__ __forceinline__ void mma_tf32(float* c, const unsigned* a, const unsigned* b) {
    asm volatile(
        "mma.sync.aligned.m16n8k8.row.col.f32.tf32.tf32.f32 "
        "{%0,%1,%2,%3}, {%4,%5,%6,%7}, {%8,%9}, {%0,%1,%2,%3};"
        : "+f"(c[0]), "+f"(c[1]), "+f"(c[2]), "+f"(c[3])
        : "r"(a[0]), "r"(a[1]), "r"(a[2]), "r"(a[3]), "r"(b[0]), "r"(b[1]));
}

// ============================================================================
// Feature GEMM (fp32 SIMT): C = X @ W, 16384x128x128.
// Output is pre-rounded to tf32 (cvt.rna) so consumers' mma fragments need
// no per-use cvt. (g_Y, g_Wh are only ever consumed by tf32 mma paths.)
// ============================================================================
template<int SRC, int DST>
__global__ __launch_bounds__(256) void feat_gemm(const float* __restrict__ Xext,
                                                 const float* __restrict__ W) {
    const float* X = (SRC == 0) ? Xext : (SRC == 1) ? (const float*)g_X1 : (const float*)g_X2;
    float* C = (DST == 0) ? (float*)g_Y : (float*)g_Wh;

    __shared__ float As[64][32];
    __shared__ float Bs[32][128];
    const int r0 = blockIdx.x * 64;
    const int rg = threadIdx.x >> 5;
    const int cg = threadIdx.x & 31;
    float acc[8][4] = {};

    for (int k0 = 0; k0 < 128; k0 += 32) {
        #pragma unroll
        for (int i = threadIdx.x; i < 512; i += 256) {
            int r = i >> 3, q = i & 7;
            *(float4*)&As[r][q*4] = *(const float4*)&X[(size_t)(r0 + r)*128 + k0 + q*4];
        }
        #pragma unroll
        for (int i = threadIdx.x; i < 1024; i += 256) {
            int r = i >> 5, q = i & 31;
            *(float4*)&Bs[r][q*4] = *(const float4*)&W[(k0 + r)*128 + q*4];
        }
        __syncthreads();
        #pragma unroll
        for (int kk = 0; kk < 32; kk++) {
            float4 bv = *(float4*)&Bs[kk][cg*4];
            #pragma unroll
            for (int r = 0; r < 8; r++) {
                float a = As[rg*8 + r][kk];
                acc[r][0] += a * bv.x; acc[r][1] += a * bv.y;
                acc[r][2] += a * bv.z; acc[r][3] += a * bv.w;
            }
        }
        __syncthreads();
    }
    #pragma unroll
    for (int r = 0; r < 8; r++) {
        float4 v;
        v.x = __uint_as_float(f2tf(acc[r][0]));
        v.y = __uint_as_float(f2tf(acc[r][1]));
        v.z = __uint_as_float(f2tf(acc[r][2]));
        v.w = __uint_as_float(f2tf(acc[r][3]));
        *(float4*)&C[(size_t)(r0 + rg*8 + r)*128 + cg*4] = v;
    }
}

// ============================================================================
// Adjacency GEMM on tensor cores (tf32), v2:
//   CTA tile 64x128, grid (16,16)=256 => single wave @ 2 CTAs/SM.
//   3-stage cp.async pipeline, 8 warps (4m x 2n), warp tile 16x64.
//   B operand (g_Y) is pre-rounded tf32 -> raw bit loads, no cvt.
// ============================================================================
#define ADJ_STAGE_BYTES (64*36*4 + 32*136*4)     // 26624
#define ADJ_SMEM_BYTES  (3*ADJ_STAGE_BYTES)      // 79872

template<int MODE>
__global__ __launch_bounds__(256, 2) void adj_gemm_tc(const float* __restrict__ adj,
                                                      const float* __restrict__ mask) {
    extern __shared__ char dynsm[];
    float (*As)[64][36]  = reinterpret_cast<float(*)[64][36]>(dynsm);
    float (*Bs)[32][136] = reinterpret_cast<float(*)[32][136]>(dynsm + 3*64*36*4);

    const int b  = blockIdx.y;
    const int r0 = blockIdx.x * 64;
    const float* A  = adj + (size_t)b*NN*NN;
    const float* Yb = (const float*)g_Y + (size_t)b*NN*HD;
    const int tid = threadIdx.x;

    auto load_stage = [&](int st, int k0) {
        #pragma unroll
        for (int i = tid; i < 512; i += 256) {
            int r = i >> 3, q = i & 7;
            cpa16(&As[st][r][q*4], &A[(size_t)(r0 + r)*NN + k0 + q*4]);
        }
        #pragma unroll
        for (int i = tid; i < 1024; i += 256) {
            int r = i >> 5, q = i & 31;
            cpa16(&Bs[st][r][q*4], &Yb[(size_t)(k0 + r)*HD + q*4]);
        }
        cpa_commit();
    };

    load_stage(0, 0);
    load_stage(1, 32);

    const int warp = tid >> 5, lane = tid & 31;
    const int wr = (warp >> 1) * 16;     // 0,16,32,48
    const int wc = (warp & 1) * 64;      // 0,64
    const int lr = lane >> 2;            // 0..7
    const int lc = lane & 3;             // 0..3

    float acc[8][4];
    #pragma unroll
    for (int n = 0; n < 8; n++)
        #pragma unroll
        for (int q = 0; q < 4; q++) acc[n][q] = 0.f;

    for (int kt = 0; kt < 32; kt++) {
        const int cur = kt % 3;
        if (kt + 2 < 32) load_stage((kt + 2) % 3, (kt + 2) * 32);
        cpa_wait<2>();
        __syncthreads();

        #pragma unroll
        for (int ks = 0; ks < 32; ks += 8) {
            unsigned af[4];
            af[0] = f2tf(As[cur][wr + lr    ][ks + lc    ]);
            af[1] = f2tf(As[cur][wr + lr + 8][ks + lc    ]);
            af[2] = f2tf(As[cur][wr + lr    ][ks + lc + 4]);
            af[3] = f2tf(As[cur][wr + lr + 8][ks + lc + 4]);
            unsigned bf[8][2];
            #pragma unroll
            for (int n = 0; n < 8; n++) {
                int c = wc + n*8 + lr;
                bf[n][0] = __float_as_uint(Bs[cur][ks + lc    ][c]);   // pre-rounded
                bf[n][1] = __float_as_uint(Bs[cur][ks + lc + 4][c]);
            }
            #pragma unroll
            for (int n = 0; n < 8; n++)
                mma_tf32(acc[n], af, bf[n]);
        }
        __syncthreads();
    }

    #pragma unroll
    for (int half = 0; half < 2; half++) {
        int row = r0 + wr + lr + half*8;
        float mk = mask[b*NN + row];
        size_t base = (size_t)b*NN*HD + (size_t)row*HD;
        #pragma unroll
        for (int n = 0; n < 8; n++) {
            int col = wc + n*8 + 2*lc;
            float v0 = fmaxf(acc[n][half*2 + 0], 0.f) * mk;
            float v1 = fmaxf(acc[n][half*2 + 1], 0.f) * mk;
            if (MODE == 1) {
                float2 x = *(const float2*)&g_X1[base + col];
                v0 += x.x; v1 += x.y;
                *(float2*)&g_X2[base + col] = make_float2(v0, v1);
            } else {
                *(float2*)&g_X1[base + col] = make_float2(v0, v1);
            }
        }
    }
}

// ============================================================================
// s1/s2 per-row dots (g_Wh is tf32-rounded; fine for scores)
// ============================================================================
__global__ __launch_bounds__(256) void s12_kernel(const float* __restrict__ a) {
    int row  = blockIdx.x * 8 + (threadIdx.x >> 5);
    int lane = threadIdx.x & 31;
    float4 x  = *(const float4*)&g_Wh[(size_t)row*128 + lane*4];
    float4 a1 = *(const float4*)&a[lane*4];
    float4 a2 = *(const float4*)&a[128 + lane*4];
    float d1 = x.x*a1.x + x.y*a1.y + x.z*a1.z + x.w*a1.w;
    float d2 = x.x*a2.x + x.y*a2.y + x.z*a2.z + x.w*a2.w;
    #pragma unroll
    for (int off = 16; off > 0; off >>= 1) {
        d1 += __shfl_xor_sync(0xffffffffu, d1, off);
        d2 += __shfl_xor_sync(0xffffffffu, d2, off);
    }
    if (lane == 0) { g_s1[row] = d1; g_s2[row] = d2; }
}

// ============================================================================
// GAT: online-softmax flash attention; P@Wh on tensor cores (no in-loop cvt:
// Ps stored pre-rounded, Wh pre-rounded in gmem).
// ============================================================================
__global__ __launch_bounds__(256) void gat_tc(const float* __restrict__ adj,
                                              const float* __restrict__ mask) {
    const int b  = blockIdx.y;
    const int i0 = blockIdx.x * 64;
    const float* Ab  = adj + (size_t)b*NN*NN;
    const float* Whb = (const float*)g_Wh + (size_t)b*NN*HD;

    __shared__ float Whs[2][32][136];
    __shared__ float Ps[64][36];
    __shared__ float scaleS[64], lS[64], s1S[64], nmiS[64];

    const int tid  = threadIdx.x;
    const int warp = tid >> 5, lane = tid & 31;
    const int m0   = (warp >> 1) * 16;
    const int wc   = (warp & 1) * 64;
    const int lr   = lane >> 2, lc = lane & 3;
    const int prow = tid >> 2, psub = tid & 3;

    if (tid < 64) {
        s1S[tid]  = g_s1[b*NN + i0 + tid];
        nmiS[tid] = mask[b*NN + i0 + tid];
    }

    auto load_wh = [&](int st, int j0) {
        #pragma unroll
        for (int i = tid; i < 1024; i += 256) {
            int r = i >> 5, q = i & 31;
            cpa16(&Whs[st][r][q*4], &Whb[(size_t)(j0 + r)*HD + q*4]);
        }
        cpa_commit();
    };

    load_wh(0, 0);

    const float* arow_base = Ab + (size_t)(i0 + prow)*NN + psub*8;
    float4 pa0 = *(const float4*)&arow_base[0];
    float4 pa1 = *(const float4*)&arow_base[4];

    float acc[8][4];
    #pragma unroll
    for (int n = 0; n < 8; n++)
        #pragma unroll
        for (int q = 0; q < 4; q++) acc[n][q] = 0.f;

    float m = -INFINITY, l = 0.f;
    __syncthreads();

    for (int jt = 0; jt < 32; jt++) {
        const int cur = jt & 1;
        const int j0  = jt * 32;
        if (jt + 1 < 32) load_wh(cur ^ 1, j0 + 32);

        // ---- softmax phase (SIMT) ----
        float s1v = s1S[prow], nmi = nmiS[prow];
        float4 s2a = *(const float4*)&g_s2[b*NN + j0 + psub*8];
        float4 s2b = *(const float4*)&g_s2[b*NN + j0 + psub*8 + 4];
        float4 nma = *(const float4*)&mask[b*NN + j0 + psub*8];
        float4 nmb = *(const float4*)&mask[b*NN + j0 + psub*8 + 4];
        float s2v[8] = {s2a.x, s2a.y, s2a.z, s2a.w, s2b.x, s2b.y, s2b.z, s2b.w};
        float nmv[8] = {nma.x, nma.y, nma.z, nma.w, nmb.x, nmb.y, nmb.z, nmb.w};
        float av[8]  = {pa0.x, pa0.y, pa0.z, pa0.w, pa1.x, pa1.y, pa1.z, pa1.w};

        float vals[8];
        float tmax = -INFINITY;
        #pragma unroll
        for (int jj = 0; jj < 8; jj++) {
            float e = s1v + s2v[jj];
            e = (e > 0.f) ? e : ALPHAV * e;
            float edge = (av[jj] > 0.f) ? (nmv[jj] * nmi) : 0.f;
            float v = (edge > 0.f) ? e : NEGV;
            vals[jj] = v;
            tmax = fmaxf(tmax, v);
        }
        tmax = fmaxf(tmax, __shfl_xor_sync(0xffffffffu, tmax, 1));
        tmax = fmaxf(tmax, __shfl_xor_sync(0xffffffffu, tmax, 2));
        float mn    = fmaxf(m, tmax);
        float scale = __expf(m - mn);
        float psum = 0.f;
        #pragma unroll
        for (int jj = 0; jj < 8; jj++) {
            float p = __expf(vals[jj] - mn);
            float pr = __uint_as_float(f2tf(p));   // rounded once; used in BOTH l and P@Wh
            Ps[prow][psub*8 + jj] = pr;
            psum += pr;
        }
        psum += __shfl_xor_sync(0xffffffffu, psum, 1);
        psum += __shfl_xor_sync(0xffffffffu, psum, 2);
        l = l * scale + psum;
        m = mn;
        if (psub == 0) scaleS[prow] = scale;

        if (jt + 1 < 32) {
            pa0 = *(const float4*)&arow_base[j0 + 32];
            pa1 = *(const float4*)&arow_base[j0 + 36];
        }

        if (jt + 1 < 32) cpa_wait<1>(); else cpa_wait<0>();
        __syncthreads();

        // ---- rescale + P @ Wh (tensor cores, zero cvt) ----
        float sc0 = scaleS[m0 + lr], sc1 = scaleS[m0 + lr + 8];
        #pragma unroll
        for (int n = 0; n < 8; n++) {
            acc[n][0] *= sc0; acc[n][1] *= sc0;
            acc[n][2] *= sc1; acc[n][3] *= sc1;
        }
        #pragma unroll
        for (int ks = 0; ks < 32; ks += 8) {
            unsigned af[4];
            af[0] = __float_as_uint(Ps[m0 + lr    ][ks + lc    ]);
            af[1] = __float_as_uint(Ps[m0 + lr + 8][ks + lc    ]);
            af[2] = __float_as_uint(Ps[m0 + lr    ][ks + lc + 4]);
            af[3] = __float_as_uint(Ps[m0 + lr + 8][ks + lc + 4]);
            unsigned bf[8][2];
            #pragma unroll
            for (int n = 0; n < 8; n++) {
                int c = wc + n*8 + lr;
                bf[n][0] = __float_as_uint(Whs[cur][ks + lc    ][c]);
                bf[n][1] = __float_as_uint(Whs[cur][ks + lc + 4][c]);
            }
            #pragma unroll
            for (int n = 0; n < 8; n++)
                mma_tf32(acc[n], af, bf[n]);
        }
        __syncthreads();
    }

    if (psub == 0) lS[prow] = l;
    __syncthreads();

    float* x3b = (float*)g_x3 + (size_t)b*NN*HD;
    #pragma unroll
    for (int half = 0; half < 2; half++) {
        int rloc = m0 + lr + half*8;
        float inv = 1.f / lS[rloc];
        float nmi = nmiS[rloc];
        size_t base = (size_t)(i0 + rloc)*HD;
        #pragma unroll
        for (int n = 0; n < 8; n++) {
            int col = wc + n*8 + 2*lc;
            float v0 = fmaxf(acc[n][half*2 + 0]*inv, 0.f) * nmi;
            float v1 = fmaxf(acc[n][half*2 + 1]*inv, 0.f) * nmi;
            *(float2*)&x3b[base + col] = make_float2(v0, v1);
        }
    }
}

// ============================================================================
// soft attention sigmoid
// ============================================================================
__global__ __launch_bounds__(256) void satt_kernel(const float* __restrict__ w_sa,
                                                   const float* __restrict__ b_sa) {
    int row  = blockIdx.x * 8 + (threadIdx.x >> 5);
    int lane = threadIdx.x & 31;
    float4 x = *(const float4*)&g_x3[(size_t)row*128 + lane*4];
    float4 w = *(const float4*)&w_sa[lane*4];
    float d = x.x*w.x + x.y*w.y + x.z*w.z + x.w*w.w;
    #pragma unroll
    for (int off = 16; off > 0; off >>= 1)
        d += __shfl_xor_sync(0xffffffffu, d, off);
    if (lane == 0) {
        float z = d + b_sa[0];
        g_satt[row] = 1.f / (1.f + __expf(-z));
    }
}

// ============================================================================
// Final layer + per-tile partial sum/max
// ============================================================================
__global__ __launch_bounds__(256) void final_gemm(const float* __restrict__ Wln,
                                                  const float* __restrict__ bln,
                                                  const float* __restrict__ mask) {
    __shared__ float As[64][32];
    __shared__ float Bs[32][128];
    __shared__ float redS[8][128];
    __shared__ float redM[8][128];
    const int r0 = blockIdx.x * 64;
    const int rg = threadIdx.x >> 5;
    const int cg = threadIdx.x & 31;
    float acc[8][4] = {};

    for (int k0 = 0; k0 < 128; k0 += 32) {
        #pragma unroll
        for (int i = threadIdx.x; i < 512; i += 256) {
            int r = i >> 3, q = i & 7;
            *(float4*)&As[r][q*4] = *(const float4*)&g_x3[(size_t)(r0 + r)*128 + k0 + q*4];
        }
        #pragma unroll
        for (int i = threadIdx.x; i < 1024; i += 256) {
            int r = i >> 5, q = i & 31;
            *(float4*)&Bs[r][q*4] = *(const float4*)&Wln[(k0 + r)*128 + q*4];
        }
        __syncthreads();
        #pragma unroll
        for (int kk = 0; kk < 32; kk++) {
            float4 bv = *(float4*)&Bs[kk][cg*4];
            #pragma unroll
            for (int r = 0; r < 8; r++) {
                float a = As[rg*8 + r][kk];
                acc[r][0] += a * bv.x; acc[r][1] += a * bv.y;
                acc[r][2] += a * bv.z; acc[r][3] += a * bv.w;
            }
        }
        __syncthreads();
    }

    float4 bl = *(const float4*)&bln[cg*4];
    float s[4]  = {0.f, 0.f, 0.f, 0.f};
    float mx[4] = {-INFINITY, -INFINITY, -INFINITY, -INFINITY};
    #pragma unroll
    for (int r = 0; r < 8; r++) {
        int row = r0 + rg*8 + r;
        float sa = g_satt[row] * mask[row];
        float v0 = fmaxf(acc[r][0] + bl.x, 0.f) * sa;
        float v1 = fmaxf(acc[r][1] + bl.y, 0.f) * sa;
        float v2 = fmaxf(acc[r][2] + bl.z, 0.f) * sa;
        float v3 = fmaxf(acc[r][3] + bl.w, 0.f) * sa;
        s[0] += v0; s[1] += v1; s[2] += v2; s[3] += v3;
        mx[0] = fmaxf(mx[0], v0); mx[1] = fmaxf(mx[1], v1);
        mx[2] = fmaxf(mx[2], v2); mx[3] = fmaxf(mx[3], v3);
    }
    #pragma unroll
    for (int c = 0; c < 4; c++) {
        redS[rg][cg*4 + c] = s[c];
        redM[rg][cg*4 + c] = mx[c];
    }
    __syncthreads();
    if (threadIdx.x < 32) {
        int bI = r0 >> 10;
        int t  = (r0 >> 6) & 15;
        #pragma unroll
        for (int c = 0; c < 4; c++) {
            int col = threadIdx.x*4 + c;
            float ss = 0.f, mm = -INFINITY;
            #pragma unroll
            for (int g = 0; g < 8; g++) {
                ss += redS[g][col];
                mm = fmaxf(mm, redM[g][col]);
            }
            g_psum[(bI*16 + t)*HD + col] = ss;
            g_pmax[(bI*16 + t)*HD + col] = mm;
        }
    }
}

__global__ void final_reduce(float* __restrict__ out) {
    int b = blockIdx.x, h = threadIdx.x;
    float s = 0.f, mx = -INFINITY;
    #pragma unroll
    for (int t = 0; t < 16; t++) {
        s += g_psum[(b*16 + t)*HD + h];
        mx = fmaxf(mx, g_pmax[(b*16 + t)*HD + h]);
    }
    out[b*HD + h] = s * mx;
}

// ============================================================================
extern "C" void kernel_launch(void* const* d_in, const int* in_sizes, int n_in,
                              void* d_out, int out_size) {
    const float* inputs = (const float*)d_in[0];
    const float* adj    = (const float*)d_in[1];
    const float* mask   = (const float*)d_in[2];
    const float* W0     = (const float*)d_in[3];
    const float* W1     = (const float*)d_in[4];
    const float* Wg     = (const float*)d_in[5];
    const float* a      = (const float*)d_in[6];
    const float* w_sa   = (const float*)d_in[7];
    const float* b_sa   = (const float*)d_in[8];
    const float* W_ln   = (const float*)d_in[9];
    const float* b_ln   = (const float*)d_in[10];
    float* out = (float*)d_out;

    cudaFuncSetAttribute(adj_gemm_tc<0>, cudaFuncAttributeMaxDynamicSharedMemorySize, ADJ_SMEM_BYTES);
    cudaFuncSetAttribute(adj_gemm_tc<1>, cudaFuncAttributeMaxDynamicSharedMemorySize, ADJ_SMEM_BYTES);

    const int ROWS = BB * NN;               // 16384
    dim3 gFeat(ROWS / 64);                  // 256
    dim3 gAdjTC(NN / 64, BB);               // (16,16) = 256 CTAs
    dim3 gGat(NN / 64, BB);                 // (16,16)
    dim3 gWarp(ROWS / 8);                   // 2048

    // x1 = relu(adj @ (inputs @ W0)) * mask
    feat_gemm<0, 0><<<gFeat, 256>>>(inputs, W0);
    adj_gemm_tc<0><<<gAdjTC, 256, ADJ_SMEM_BYTES>>>(adj, mask);
    // x2 = x1 + relu(adj @ (x1 @ W1)) * mask
    feat_gemm<1, 0><<<gFeat, 256>>>(nullptr, W1);
    adj_gemm_tc<1><<<gAdjTC, 256, ADJ_SMEM_BYTES>>>(adj, mask);
    // GAT
    feat_gemm<2, 1><<<gFeat, 256>>>(nullptr, Wg);   // Wh = x2 @ Wg (pre-rounded)
    s12_kernel<<<gWarp, 256>>>(a);
    gat_tc<<<gGat, 256>>>(adj, mask);
    // epilogue
    satt_kernel<<<gWarp, 256>>>(w_sa, b_sa);
    final_gemm<<<gFeat, 256>>>(W_ln, b_ln, mask);
    final_reduce<<<BB, HD>>>(out);
}